// round 9
// baseline (speedup 1.0000x reference)
#include <cuda_runtime.h>
#include <math.h>

#define BATCH   256
#define NPTS    20000
#define TSTEPS  10
#define LAT     10
#define BPB     5              // integrate blocks per batch
#define PPB     (NPTS / BPB)   // 4000 points per block
#define ITHREADS 512
#define COEF_PER_BATCH (TSTEPS * 256 * 8)   // 20480 floats = 80 KB
#define NSBLK   40             // sort blocks: 40*512 >= NPTS

// ---- device scratch (no allocations allowed) ----
__device__ float  g_coef[BATCH * COEF_PER_BATCH];   // [b][t][cell(16x16)][8]
__device__ int    g_order[NPTS];
__device__ float2 g_tps[NPTS];
__device__ int    g_bhist[NSBLK][256];   // per-block cell histograms
__device__ int    g_bbase[NSBLK][256];   // per-block scatter bases

__device__ __forceinline__ int cell_of(float2 P) {
    int ui = min(max(__float2int_rd((P.x + 2.5f) * 3.0f), 0), 15);
    int vi = min(max(__float2int_rd((P.y + 2.5f) * 3.0f), 0), 15);
    return ui * 16 + vi;
}

// ============================================================================
// Counting sort by initial grid cell — 3 kernels, NO global atomics.
// Stores overwrite g_bhist/g_bbase each run -> deterministic under graph replay.
// Intra-cell order is nondeterministic but output values are order-independent.
// ============================================================================
__global__ void sort_count_kernel(const float* __restrict__ tpl)
{
    __shared__ int lh[256];
    const int tid = threadIdx.x;
    if (tid < 256) lh[tid] = 0;
    __syncthreads();
    int p = blockIdx.x * 512 + tid;
    if (p < NPTS) atomicAdd(&lh[cell_of(((const float2*)tpl)[p])], 1);
    __syncthreads();
    if (tid < 256) g_bhist[blockIdx.x][tid] = lh[tid];
}

__global__ void sort_scan_kernel()
{
    __shared__ int tmp[256];
    const int c = threadIdx.x;
    int total = 0;
    #pragma unroll
    for (int bk = 0; bk < NSBLK; bk++) total += g_bhist[bk][c];   // coalesced
    tmp[c] = total;
    __syncthreads();
    #pragma unroll
    for (int off = 1; off < 256; off <<= 1) {
        int x = (c >= off) ? tmp[c - off] : 0;
        __syncthreads();
        tmp[c] += x;
        __syncthreads();
    }
    int running = tmp[c] - total;   // exclusive prefix over cells
    #pragma unroll
    for (int bk = 0; bk < NSBLK; bk++) {
        g_bbase[bk][c] = running;
        running += g_bhist[bk][c];
    }
}

__global__ void sort_scatter_kernel(const float* __restrict__ tpl)
{
    __shared__ int lh[256];     // local cursor
    __shared__ int lbase[256];  // this block's global bases
    const int tid = threadIdx.x;
    if (tid < 256) {
        lh[tid] = 0;
        lbase[tid] = g_bbase[blockIdx.x][tid];
    }
    __syncthreads();
    int p = blockIdx.x * 512 + tid;
    if (p < NPTS) {
        float2 P = ((const float2*)tpl)[p];
        int c = cell_of(P);
        int idx = lbase[c] + atomicAdd(&lh[c], 1);
        g_order[idx] = p;
        g_tps[idx] = P;
    }
}

// ============================================================================
// Fused encoder + decoder + coefficient build. One block per batch, 256 thr.
// Shared-memory union (12288 floats = 48 KB), region lifetimes:
//   E1:  OBS[0,8192)  A1[8192,12288)
//   E2:  A2[0,2048)   E3: A3[2048,3072)   E4: A4[3072,3328)
//   LIN: RED[11800,11880), Z[11900,11910)
//   DEC: ZD[11910,11974), H[0,640), O1[640,1920), O2[1920,4480), VF[4480,9600)
// ============================================================================
#define OBS_  0
#define A1_   8192
#define A2_   0
#define A3_   2048
#define A4_   3072
#define RED_  11800
#define Z_    11900
#define ZD_   11910
#define H_    0
#define O1_   640
#define O2_   1920
#define VF_   4480

__global__ __launch_bounds__(256)
void encdec_kernel(const float* __restrict__ obs,
    const float* __restrict__ w1, const float* __restrict__ b1,
    const float* __restrict__ w2, const float* __restrict__ b2,
    const float* __restrict__ w3, const float* __restrict__ b3,
    const float* __restrict__ w4, const float* __restrict__ b4,
    const float* __restrict__ lw, const float* __restrict__ lb,
    const float* __restrict__ dlw,
    const float* __restrict__ dw1, const float* __restrict__ dw2,
    const float* __restrict__ dw3)
{
    __shared__ float S[12288];
    const int b = blockIdx.x;
    const int tid = threadIdx.x;

    {
        const float4* src = (const float4*)(obs + (size_t)b * 8192);
        float4* dst = (float4*)&S[OBS_];
        #pragma unroll
        for (int i = 0; i < 8; i++) dst[tid + i * 256] = src[tid + i * 256];
    }
    __syncthreads();

    // layer1: [2,64,64] -> [4,32,32]
    #pragma unroll
    for (int it = 0; it < 16; it++) {
        int n = tid + it * 256;
        int o = n >> 10, r = (n >> 5) & 31, c = n & 31;
        float s = b1[o];
        #pragma unroll
        for (int ci = 0; ci < 2; ci++)
            #pragma unroll
            for (int m = 0; m < 2; m++) {
                float2 xv = ((const float2*)&S[OBS_ + ci*4096 + (2*r+m)*64])[c];
                s += xv.x * w1[o*8 + ci*4 + m*2] + xv.y * w1[o*8 + ci*4 + m*2 + 1];
            }
        S[A1_ + n] = tanhf(s);
    }
    __syncthreads();
    // layer2: -> [8,16,16]
    #pragma unroll
    for (int it = 0; it < 8; it++) {
        int n = tid + it * 256;
        int o = n >> 8, r = (n >> 4) & 15, c = n & 15;
        float s = b2[o];
        #pragma unroll
        for (int ci = 0; ci < 4; ci++)
            #pragma unroll
            for (int m = 0; m < 2; m++) {
                float2 xv = ((const float2*)&S[A1_ + ci*1024 + (2*r+m)*32])[c];
                s += xv.x * w2[o*16 + ci*4 + m*2] + xv.y * w2[o*16 + ci*4 + m*2 + 1];
            }
        S[A2_ + n] = tanhf(s);
    }
    __syncthreads();
    // layer3: -> [16,8,8]
    #pragma unroll
    for (int it = 0; it < 4; it++) {
        int n = tid + it * 256;
        int o = n >> 6, r = (n >> 3) & 7, c = n & 7;
        float s = b3[o];
        #pragma unroll
        for (int ci = 0; ci < 8; ci++)
            #pragma unroll
            for (int m = 0; m < 2; m++) {
                float2 xv = ((const float2*)&S[A2_ + ci*256 + (2*r+m)*16])[c];
                s += xv.x * w3[o*32 + ci*4 + m*2] + xv.y * w3[o*32 + ci*4 + m*2 + 1];
            }
        S[A3_ + n] = tanhf(s);
    }
    __syncthreads();
    // layer4: -> [16,4,4]
    if (tid < 256) {
        int n = tid;
        int o = n >> 4, r = (n >> 2) & 3, c = n & 3;
        float s = b4[o];
        #pragma unroll
        for (int ci = 0; ci < 16; ci++)
            #pragma unroll
            for (int m = 0; m < 2; m++) {
                float2 xv = ((const float2*)&S[A3_ + ci*64 + (2*r+m)*8])[c];
                s += xv.x * w4[o*64 + ci*4 + m*2] + xv.y * w4[o*64 + ci*4 + m*2 + 1];
            }
        S[A4_ + n] = tanhf(s);
    }
    __syncthreads();
    if (tid < 80) {
        int l = tid >> 3, seg = tid & 7;
        float s = 0.f;
        #pragma unroll
        for (int k = 0; k < 32; k++)
            s += S[A4_ + seg*32 + k] * lw[l*256 + seg*32 + k];
        S[RED_ + tid] = s;
    }
    __syncthreads();
    if (tid < LAT) {
        float s = lb[tid];
        #pragma unroll
        for (int k = 0; k < 8; k++) s += S[RED_ + tid*8 + k];
        S[Z_ + tid] = s;
    }
    __syncthreads();

    // ---- decoder, all T-1 time scales in one pass ----
    if (tid < 64) {
        float s = 0.f;
        #pragma unroll
        for (int l = 0; l < LAT; l++) s += S[Z_ + l] * dlw[tid*LAT + l];
        S[ZD_ + tid] = s;
    }
    __syncthreads();
    for (int n = tid; n < 640; n += 256) {
        int t = n >> 6, k = n & 63;
        S[H_ + n] = tanhf(0.1f * (float)(t + 1) * S[ZD_ + k]);
    }
    __syncthreads();
    for (int n0 = tid; n0 < 1280; n0 += 256) {
        int t = n0 >> 7, r = n0 & 127;
        int o = r >> 4, p = (r >> 2) & 3, q = r & 3;
        float s = 0.f;
        #pragma unroll
        for (int c = 0; c < 16; c++)
            s += S[H_ + t*64 + c*4 + (p>>1)*2 + (q>>1)]
               * dw1[c*32 + o*4 + (1-(p&1))*2 + (1-(q&1))];
        S[O1_ + n0] = tanhf(s);
    }
    __syncthreads();
    for (int n0 = tid; n0 < 2560; n0 += 256) {
        int t = n0 >> 8, r = n0 & 255;
        int o = r >> 6, p = (r >> 3) & 7, q = r & 7;
        float s = 0.f;
        #pragma unroll
        for (int c = 0; c < 8; c++)
            s += S[O1_ + t*128 + c*16 + (p>>1)*4 + (q>>1)]
               * dw2[c*16 + o*4 + (1-(p&1))*2 + (1-(q&1))];
        S[O2_ + n0] = tanhf(s);
    }
    __syncthreads();
    for (int n0 = tid; n0 < 5120; n0 += 256) {
        int t = n0 >> 9, r = n0 & 511;
        int o = r >> 8, p = (r >> 4) & 15, q = r & 15;
        float s = 0.f;
        #pragma unroll
        for (int c = 0; c < 4; c++)
            s += S[O2_ + t*256 + c*64 + (p>>1)*8 + (q>>1)]
               * dw3[c*8 + o*4 + (1-(p&1))*2 + (1-(q&1))];
        S[VF_ + n0] = s;
    }
    __syncthreads();
    float* cc = g_coef + (size_t)b * COEF_PER_BATCH;
    const float Sc = 0.3f;
    for (int n0 = tid; n0 < 2560; n0 += 256) {
        int t = n0 >> 8, cell = n0 & 255;
        int i = cell >> 4, j = cell & 15;
        int i2 = min(i + 1, 15), j2 = min(j + 1, 15);
        const float* vf = &S[VF_ + t*512];
        float v00x = vf[i*16 + j],    v00y = vf[256 + i*16 + j];
        float v10x = vf[i2*16 + j],   v10y = vf[256 + i2*16 + j];
        float v01x = vf[i*16 + j2],   v01y = vf[256 + i*16 + j2];
        float v11x = vf[i2*16 + j2],  v11y = vf[256 + i2*16 + j2];
        float4 ca = make_float4(Sc*v00x, Sc*v00y, Sc*(v10x - v00x), Sc*(v10y - v00y));
        float4 cb = make_float4(Sc*(v01x - v00x), Sc*(v01y - v00y),
                                Sc*(v11x - v01x - v10x + v00x),
                                Sc*(v11y - v01y - v10y + v00y));
        float4* d = (float4*)(cc + (t*256 + cell) * 8);
        d[0] = ca; d[1] = cb;
    }
}

// ============================================================================
// Integration over cell-sorted points, 2 points per thread for ILP.
// Float-domain floor + flat-index guard; guard only protects smem bounds.
// ============================================================================
__device__ __forceinline__ void euler_step(const float* sc, int t,
                                           float& u, float& v)
{
    float uf = floorf(u), vf = floorf(v);
    float fu = u - uf,    fv = v - vf;
    float idxf = fminf(fmaxf(uf * 16.0f + vf, 0.0f), 255.0f);
    int idx = __float2int_rz(idxf);
    const float4* c = (const float4*)&sc[(t << 11) + (idx << 3)];
    float4 ca = c[0];   // c00x c00y c10x c10y
    float4 cb = c[1];   // c01x c01y c11x c11y
    float fufv = fu * fv;
    u += ca.x + fu*ca.z + fv*cb.x + fufv*cb.z;
    v += ca.y + fu*ca.w + fv*cb.y + fufv*cb.w;
}

__global__ __launch_bounds__(ITHREADS, 2)
void integrate_kernel(float* __restrict__ out)
{
    extern __shared__ float sc[];     // 20480 floats: [t][cell][8]
    const int b   = blockIdx.x / BPB;
    const int blk = blockIdx.x % BPB;

    const float4* src = (const float4*)(g_coef + (size_t)b * COEF_PER_BATCH);
    float4* dst = (float4*)sc;
    #pragma unroll
    for (int i = 0; i < COEF_PER_BATCH / 4 / ITHREADS; i++)
        dst[threadIdx.x + i * ITHREADS] = src[threadIdx.x + i * ITHREADS];
    __syncthreads();

    float2* op2 = (float2*)out + (size_t)b * NPTS;
    const int pend = blk * PPB + PPB;
    for (int p0 = blk * PPB + threadIdx.x; p0 < pend; p0 += 2 * ITHREADS) {
        const int p1 = p0 + ITHREADS;
        const bool has1 = p1 < pend;
        float2 A = g_tps[p0];
        float2 Bp = has1 ? g_tps[p1] : make_float2(0.f, 0.f);
        int oa = g_order[p0];
        int ob = has1 ? g_order[p1] : 0;
        float ua = (A.x + 2.5f) * 3.0f,  va = (A.y + 2.5f) * 3.0f;
        float ub = (Bp.x + 2.5f) * 3.0f, vb = (Bp.y + 2.5f) * 3.0f;
        #pragma unroll
        for (int t = 0; t < TSTEPS; t++) {
            euler_step(sc, t, ua, va);
            euler_step(sc, t, ub, vb);
        }
        op2[oa] = make_float2(ua * (1.0f/3.0f) - 2.5f, va * (1.0f/3.0f) - 2.5f);
        if (has1)
            op2[ob] = make_float2(ub * (1.0f/3.0f) - 2.5f, vb * (1.0f/3.0f) - 2.5f);
    }
}

// ============================================================================
extern "C" void kernel_launch(void* const* d_in, const int* in_sizes, int n_in,
                              void* d_out, int out_size)
{
    const float* obs   = (const float*)d_in[0];
    const float* tpl   = (const float*)d_in[1];
    const float* ew1   = (const float*)d_in[2];
    const float* eb1   = (const float*)d_in[3];
    const float* ew2   = (const float*)d_in[4];
    const float* eb2   = (const float*)d_in[5];
    const float* ew3   = (const float*)d_in[6];
    const float* eb3   = (const float*)d_in[7];
    const float* ew4   = (const float*)d_in[8];
    const float* eb4   = (const float*)d_in[9];
    const float* elw   = (const float*)d_in[10];
    const float* elb   = (const float*)d_in[11];
    const float* dlw   = (const float*)d_in[12];
    const float* dw1   = (const float*)d_in[13];
    const float* dw2   = (const float*)d_in[14];
    const float* dw3   = (const float*)d_in[15];
    float* out = (float*)d_out;

    cudaFuncSetAttribute(integrate_kernel,
                         cudaFuncAttributeMaxDynamicSharedMemorySize,
                         COEF_PER_BATCH * 4);

    sort_count_kernel<<<NSBLK, 512>>>(tpl);
    sort_scan_kernel<<<1, 256>>>();
    sort_scatter_kernel<<<NSBLK, 512>>>(tpl);
    encdec_kernel<<<BATCH, 256>>>(obs, ew1, eb1, ew2, eb2, ew3, eb3, ew4, eb4,
                                  elw, elb, dlw, dw1, dw2, dw3);
    integrate_kernel<<<BATCH * BPB, ITHREADS, COEF_PER_BATCH * 4>>>(out);
}

// round 11
// speedup vs baseline: 1.0010x; 1.0010x over previous
#include <cuda_runtime.h>
#include <math.h>

#define BATCH   256
#define NPTS    20000
#define TSTEPS  10
#define LAT     10
#define BPB     5              // integrate blocks per batch
#define PPB     (NPTS / BPB)   // 4000 points per block
#define ITHREADS 512
#define ETHREADS 512
#define COEF_PER_BATCH (TSTEPS * 256 * 8)   // 20480 floats = 80 KB
#define NSBLK   40             // sort blocks: 40*512 >= NPTS

// ---- device scratch (no allocations allowed) ----
__device__ float  g_coef[BATCH * COEF_PER_BATCH];   // [b][t][cell(16x16)][8]
__device__ int    g_order[NPTS];
__device__ float2 g_tps[NPTS];
__device__ int    g_bhist[NSBLK][256];   // per-block cell histograms
__device__ int    g_bbase[NSBLK][256];   // per-block scatter bases

__device__ __forceinline__ float tanh_fast(float x) {
    float y;
    asm("tanh.approx.f32 %0, %1;" : "=f"(y) : "f"(x));
    return y;
}

__device__ __forceinline__ int cell_of(float2 P) {
    int ui = min(max(__float2int_rd((P.x + 2.5f) * 3.0f), 0), 15);
    int vi = min(max(__float2int_rd((P.y + 2.5f) * 3.0f), 0), 15);
    return ui * 16 + vi;
}

// ============================================================================
// Counting sort by initial grid cell — 3 kernels, NO global atomics.
// ============================================================================
__global__ void sort_count_kernel(const float* __restrict__ tpl)
{
    __shared__ int lh[256];
    const int tid = threadIdx.x;
    if (tid < 256) lh[tid] = 0;
    __syncthreads();
    int p = blockIdx.x * 512 + tid;
    if (p < NPTS) atomicAdd(&lh[cell_of(((const float2*)tpl)[p])], 1);
    __syncthreads();
    if (tid < 256) g_bhist[blockIdx.x][tid] = lh[tid];
}

__global__ void sort_scan_kernel()
{
    __shared__ int tmp[256];
    const int c = threadIdx.x;
    int total = 0;
    #pragma unroll
    for (int bk = 0; bk < NSBLK; bk++) total += g_bhist[bk][c];
    tmp[c] = total;
    __syncthreads();
    #pragma unroll
    for (int off = 1; off < 256; off <<= 1) {
        int x = (c >= off) ? tmp[c - off] : 0;
        __syncthreads();
        tmp[c] += x;
        __syncthreads();
    }
    int running = tmp[c] - total;   // exclusive prefix over cells
    #pragma unroll
    for (int bk = 0; bk < NSBLK; bk++) {
        g_bbase[bk][c] = running;
        running += g_bhist[bk][c];
    }
}

__global__ void sort_scatter_kernel(const float* __restrict__ tpl)
{
    __shared__ int lh[256];     // local cursor
    __shared__ int lbase[256];  // this block's global bases
    const int tid = threadIdx.x;
    if (tid < 256) {
        lh[tid] = 0;
        lbase[tid] = g_bbase[blockIdx.x][tid];
    }
    __syncthreads();
    int p = blockIdx.x * 512 + tid;
    if (p < NPTS) {
        float2 P = ((const float2*)tpl)[p];
        int c = cell_of(P);
        int idx = lbase[c] + atomicAdd(&lh[c], 1);
        g_order[idx] = p;
        g_tps[idx] = P;
    }
}

// ============================================================================
// Fused encoder + decoder + coefficient build. One block per batch, 512 thr,
// HW tanh.approx. Shared-memory union (12288 floats = 48 KB):
//   E1:  OBS[0,8192)  A1[8192,12288)
//   E2:  A2[0,2048)   E3: A3[2048,3072)   E4: A4[3072,3328)
//   LIN: RED[11800,11880), Z[11900,11910)
//   DEC: ZD[11910,11974), H[0,640), O1[640,1920), O2[1920,4480), VF[4480,9600)
// ============================================================================
#define OBS_  0
#define A1_   8192
#define A2_   0
#define A3_   2048
#define A4_   3072
#define RED_  11800
#define Z_    11900
#define ZD_   11910
#define H_    0
#define O1_   640
#define O2_   1920
#define VF_   4480

__global__ __launch_bounds__(ETHREADS)
void encdec_kernel(const float* __restrict__ obs,
    const float* __restrict__ w1, const float* __restrict__ b1,
    const float* __restrict__ w2, const float* __restrict__ b2,
    const float* __restrict__ w3, const float* __restrict__ b3,
    const float* __restrict__ w4, const float* __restrict__ b4,
    const float* __restrict__ lw, const float* __restrict__ lb,
    const float* __restrict__ dlw,
    const float* __restrict__ dw1, const float* __restrict__ dw2,
    const float* __restrict__ dw3)
{
    __shared__ float S[12288];
    const int b = blockIdx.x;
    const int tid = threadIdx.x;

    {
        const float4* src = (const float4*)(obs + (size_t)b * 8192);
        float4* dst = (float4*)&S[OBS_];
        #pragma unroll
        for (int i = 0; i < 4; i++) dst[tid + i * ETHREADS] = src[tid + i * ETHREADS];
    }
    __syncthreads();

    // layer1: [2,64,64] -> [4,32,32]  (4096 outputs)
    #pragma unroll
    for (int it = 0; it < 8; it++) {
        int n = tid + it * ETHREADS;
        int o = n >> 10, r = (n >> 5) & 31, c = n & 31;
        float s = b1[o];
        #pragma unroll
        for (int ci = 0; ci < 2; ci++)
            #pragma unroll
            for (int m = 0; m < 2; m++) {
                float2 xv = ((const float2*)&S[OBS_ + ci*4096 + (2*r+m)*64])[c];
                s += xv.x * w1[o*8 + ci*4 + m*2] + xv.y * w1[o*8 + ci*4 + m*2 + 1];
            }
        S[A1_ + n] = tanh_fast(s);
    }
    __syncthreads();
    // layer2: -> [8,16,16]  (2048)
    #pragma unroll
    for (int it = 0; it < 4; it++) {
        int n = tid + it * ETHREADS;
        int o = n >> 8, r = (n >> 4) & 15, c = n & 15;
        float s = b2[o];
        #pragma unroll
        for (int ci = 0; ci < 4; ci++)
            #pragma unroll
            for (int m = 0; m < 2; m++) {
                float2 xv = ((const float2*)&S[A1_ + ci*1024 + (2*r+m)*32])[c];
                s += xv.x * w2[o*16 + ci*4 + m*2] + xv.y * w2[o*16 + ci*4 + m*2 + 1];
            }
        S[A2_ + n] = tanh_fast(s);
    }
    __syncthreads();
    // layer3: -> [16,8,8]  (1024)
    #pragma unroll
    for (int it = 0; it < 2; it++) {
        int n = tid + it * ETHREADS;
        int o = n >> 6, r = (n >> 3) & 7, c = n & 7;
        float s = b3[o];
        #pragma unroll
        for (int ci = 0; ci < 8; ci++)
            #pragma unroll
            for (int m = 0; m < 2; m++) {
                float2 xv = ((const float2*)&S[A2_ + ci*256 + (2*r+m)*16])[c];
                s += xv.x * w3[o*32 + ci*4 + m*2] + xv.y * w3[o*32 + ci*4 + m*2 + 1];
            }
        S[A3_ + n] = tanh_fast(s);
    }
    __syncthreads();
    // layer4: -> [16,4,4]  (256)
    if (tid < 256) {
        int n = tid;
        int o = n >> 4, r = (n >> 2) & 3, c = n & 3;
        float s = b4[o];
        #pragma unroll
        for (int ci = 0; ci < 16; ci++)
            #pragma unroll
            for (int m = 0; m < 2; m++) {
                float2 xv = ((const float2*)&S[A3_ + ci*64 + (2*r+m)*8])[c];
                s += xv.x * w4[o*64 + ci*4 + m*2] + xv.y * w4[o*64 + ci*4 + m*2 + 1];
            }
        S[A4_ + n] = tanh_fast(s);
    }
    __syncthreads();
    if (tid < 80) {
        int l = tid >> 3, seg = tid & 7;
        float s = 0.f;
        #pragma unroll
        for (int k = 0; k < 32; k++)
            s += S[A4_ + seg*32 + k] * lw[l*256 + seg*32 + k];
        S[RED_ + tid] = s;
    }
    __syncthreads();
    if (tid < LAT) {
        float s = lb[tid];
        #pragma unroll
        for (int k = 0; k < 8; k++) s += S[RED_ + tid*8 + k];
        S[Z_ + tid] = s;
    }
    __syncthreads();

    // ---- decoder, all T-1 time scales in one pass ----
    if (tid < 64) {
        float s = 0.f;
        #pragma unroll
        for (int l = 0; l < LAT; l++) s += S[Z_ + l] * dlw[tid*LAT + l];
        S[ZD_ + tid] = s;
    }
    __syncthreads();
    for (int n = tid; n < 640; n += ETHREADS) {
        int t = n >> 6, k = n & 63;
        S[H_ + n] = tanh_fast(0.1f * (float)(t + 1) * S[ZD_ + k]);
    }
    __syncthreads();
    for (int n0 = tid; n0 < 1280; n0 += ETHREADS) {
        int t = n0 >> 7, r = n0 & 127;
        int o = r >> 4, p = (r >> 2) & 3, q = r & 3;
        float s = 0.f;
        #pragma unroll
        for (int c = 0; c < 16; c++)
            s += S[H_ + t*64 + c*4 + (p>>1)*2 + (q>>1)]
               * dw1[c*32 + o*4 + (1-(p&1))*2 + (1-(q&1))];
        S[O1_ + n0] = tanh_fast(s);
    }
    __syncthreads();
    for (int n0 = tid; n0 < 2560; n0 += ETHREADS) {
        int t = n0 >> 8, r = n0 & 255;
        int o = r >> 6, p = (r >> 3) & 7, q = r & 7;
        float s = 0.f;
        #pragma unroll
        for (int c = 0; c < 8; c++)
            s += S[O1_ + t*128 + c*16 + (p>>1)*4 + (q>>1)]
               * dw2[c*16 + o*4 + (1-(p&1))*2 + (1-(q&1))];
        S[O2_ + n0] = tanh_fast(s);
    }
    __syncthreads();
    for (int n0 = tid; n0 < 5120; n0 += ETHREADS) {
        int t = n0 >> 9, r = n0 & 511;
        int o = r >> 8, p = (r >> 4) & 15, q = r & 15;
        float s = 0.f;
        #pragma unroll
        for (int c = 0; c < 4; c++)
            s += S[O2_ + t*256 + c*64 + (p>>1)*8 + (q>>1)]
               * dw3[c*8 + o*4 + (1-(p&1))*2 + (1-(q&1))];
        S[VF_ + n0] = s;
    }
    __syncthreads();
    float* cc = g_coef + (size_t)b * COEF_PER_BATCH;
    const float Sc = 0.3f;
    for (int n0 = tid; n0 < 2560; n0 += ETHREADS) {
        int t = n0 >> 8, cell = n0 & 255;
        int i = cell >> 4, j = cell & 15;
        int i2 = min(i + 1, 15), j2 = min(j + 1, 15);
        const float* vf = &S[VF_ + t*512];
        float v00x = vf[i*16 + j],    v00y = vf[256 + i*16 + j];
        float v10x = vf[i2*16 + j],   v10y = vf[256 + i2*16 + j];
        float v01x = vf[i*16 + j2],   v01y = vf[256 + i*16 + j2];
        float v11x = vf[i2*16 + j2],  v11y = vf[256 + i2*16 + j2];
        float4 ca = make_float4(Sc*v00x, Sc*v00y, Sc*(v10x - v00x), Sc*(v10y - v00y));
        float4 cb = make_float4(Sc*(v01x - v00x), Sc*(v01y - v00y),
                                Sc*(v11x - v01x - v10x + v00x),
                                Sc*(v11y - v01y - v10y + v00y));
        float4* d = (float4*)(cc + (t*256 + cell) * 8);
        d[0] = ca; d[1] = cb;
    }
}

// ============================================================================
// Integration over cell-sorted points, 2 points per thread for ILP.
// ============================================================================
__device__ __forceinline__ void euler_step(const float* sc, int t,
                                           float& u, float& v)
{
    float uf = floorf(u), vf = floorf(v);
    float fu = u - uf,    fv = v - vf;
    float idxf = fminf(fmaxf(uf * 16.0f + vf, 0.0f), 255.0f);
    int idx = __float2int_rz(idxf);
    const float4* c = (const float4*)&sc[(t << 11) + (idx << 3)];
    float4 ca = c[0];   // c00x c00y c10x c10y
    float4 cb = c[1];   // c01x c01y c11x c11y
    float fufv = fu * fv;
    u += ca.x + fu*ca.z + fv*cb.x + fufv*cb.z;
    v += ca.y + fu*ca.w + fv*cb.y + fufv*cb.w;
}

__global__ __launch_bounds__(ITHREADS, 2)
void integrate_kernel(float* __restrict__ out)
{
    extern __shared__ float sc[];     // 20480 floats: [t][cell][8]
    const int b   = blockIdx.x / BPB;
    const int blk = blockIdx.x % BPB;

    const float4* src = (const float4*)(g_coef + (size_t)b * COEF_PER_BATCH);
    float4* dst = (float4*)sc;
    #pragma unroll
    for (int i = 0; i < COEF_PER_BATCH / 4 / ITHREADS; i++)
        dst[threadIdx.x + i * ITHREADS] = src[threadIdx.x + i * ITHREADS];
    __syncthreads();

    float2* op2 = (float2*)out + (size_t)b * NPTS;
    const int pend = blk * PPB + PPB;
    for (int p0 = blk * PPB + threadIdx.x; p0 < pend; p0 += 2 * ITHREADS) {
        const int p1 = p0 + ITHREADS;
        const bool has1 = p1 < pend;
        float2 A = g_tps[p0];
        float2 Bp = has1 ? g_tps[p1] : make_float2(0.f, 0.f);
        int oa = g_order[p0];
        int ob = has1 ? g_order[p1] : 0;
        float ua = (A.x + 2.5f) * 3.0f,  va = (A.y + 2.5f) * 3.0f;
        float ub = (Bp.x + 2.5f) * 3.0f, vb = (Bp.y + 2.5f) * 3.0f;
        #pragma unroll
        for (int t = 0; t < TSTEPS; t++) {
            euler_step(sc, t, ua, va);
            euler_step(sc, t, ub, vb);
        }
        op2[oa] = make_float2(ua * (1.0f/3.0f) - 2.5f, va * (1.0f/3.0f) - 2.5f);
        if (has1)
            op2[ob] = make_float2(ub * (1.0f/3.0f) - 2.5f, vb * (1.0f/3.0f) - 2.5f);
    }
}

// ============================================================================
extern "C" void kernel_launch(void* const* d_in, const int* in_sizes, int n_in,
                              void* d_out, int out_size)
{
    const float* obs   = (const float*)d_in[0];
    const float* tpl   = (const float*)d_in[1];
    const float* ew1   = (const float*)d_in[2];
    const float* eb1   = (const float*)d_in[3];
    const float* ew2   = (const float*)d_in[4];
    const float* eb2   = (const float*)d_in[5];
    const float* ew3   = (const float*)d_in[6];
    const float* eb3   = (const float*)d_in[7];
    const float* ew4   = (const float*)d_in[8];
    const float* eb4   = (const float*)d_in[9];
    const float* elw   = (const float*)d_in[10];
    const float* elb   = (const float*)d_in[11];
    const float* dlw   = (const float*)d_in[12];
    const float* dw1   = (const float*)d_in[13];
    const float* dw2   = (const float*)d_in[14];
    const float* dw3   = (const float*)d_in[15];
    float* out = (float*)d_out;

    cudaFuncSetAttribute(integrate_kernel,
                         cudaFuncAttributeMaxDynamicSharedMemorySize,
                         COEF_PER_BATCH * 4);

    sort_count_kernel<<<NSBLK, 512>>>(tpl);
    sort_scan_kernel<<<1, 256>>>();
    sort_scatter_kernel<<<NSBLK, 512>>>(tpl);
    encdec_kernel<<<BATCH, ETHREADS>>>(obs, ew1, eb1, ew2, eb2, ew3, eb3, ew4, eb4,
                                       elw, elb, dlw, dw1, dw2, dw3);
    integrate_kernel<<<BATCH * BPB, ITHREADS, COEF_PER_BATCH * 4>>>(out);
}